// round 5
// baseline (speedup 1.0000x reference)
#include <cuda_runtime.h>

#define NSAMP 65536
#define EPSF 1e-8f
#define BLOCK_THREADS 128
#define NBLOCKS 760              // 5 CTAs/SM * 152 SMs (GB300): one resident wave

// Warp-per-sample, register-resident persistent kernel.
// Lane l -> (o = l>>1, i-half h = l&1); lane owns pairs (o, i = h*8+k), k=0..7.
// Scaled quaternions (32 regs) persist in registers; translations live in
// shared as float4[k][lane] (one conflict-free LDS.128 per k-step).

__global__ void __launch_bounds__(BLOCK_THREADS, 5)
caps_quat_kernel(const float* __restrict__ x,
                 const float* __restrict__ quats,
                 const float* __restrict__ scale,
                 const float* __restrict__ trans,
                 const float* __restrict__ bias,
                 const float* __restrict__ beta,
                 const float* __restrict__ alpha,
                 float* __restrict__ out)
{
    __shared__ float4 sT[8 * 32];     // [k][lane] -> (t1, t2, t3, 0)

    const int tid  = threadIdx.x;
    const int lane = tid & 31;
    const int h    = lane & 1;       // i-half
    const int o    = lane >> 1;      // output capsule

    // ---- translations into shared (each CTA builds its own copy) ----
    for (int s = tid; s < 256; s += BLOCK_THREADS) {
        const int kp = s >> 5, lp = s & 31;
        const int pi = (lp >> 1) * 16 + ((lp & 1) << 3) + kp;
        sT[s] = make_float4(trans[pi * 3 + 0], trans[pi * 3 + 1], trans[pi * 3 + 2], 0.0f);
    }

    // ---- persistent per-lane constants: scaled quaternions (32 regs) ----
    float qw[8], qx[8], qy[8], qz[8];
    const float4* __restrict__ q4 = (const float4*)quats;
#pragma unroll
    for (int k = 0; k < 8; k++) {
        const int pi = o * 16 + h * 8 + k;
        const float4 q = __ldg(&q4[pi]);
        const float f = rsqrtf(fmaf(q.x, q.x, fmaf(q.y, q.y, fmaf(q.z, q.z, q.w * q.w))) + EPSF)
                        * __ldg(&scale[pi]);
        qw[k] = q.x * f; qx[k] = q.y * f; qy[k] = q.z * f; qz[k] = q.w * f;
    }
    const float bet = __ldg(&beta[o]);
    const float ab  = __ldg(&alpha[o]) + __ldg(&bias[o]);

    __syncthreads();

    const float4* __restrict__ x4   = (const float4*)x + h * 8;
    float4* __restrict__       out4 = (float4*)out;

    const int warp       = blockIdx.x * (BLOCK_THREADS / 32) + (tid >> 5);
    const int warpStride = NBLOCKS * (BLOCK_THREADS / 32);

#pragma unroll 1
    for (int n = warp; n < NSAMP; n += warpStride) {
        // ---- votes: Hamilton product, quaternions from regs, trans from shared ----
        float vw[8], vx[8], vy[8], vz[8];
#pragma unroll
        for (int k = 0; k < 8; k++) {
            const float4 X = __ldg(&x4[n * 16 + k]);
            const float4 T = sT[k * 32 + lane];
            vw[k] = fmaf(qw[k], X.x, fmaf(-qx[k], X.y, fmaf(-qy[k], X.z, -qz[k] * X.w)));
            vx[k] = fmaf(qw[k], X.y, fmaf( qx[k], X.x, fmaf( qy[k], X.w, fmaf(-qz[k], X.z, T.x))));
            vy[k] = fmaf(qw[k], X.z, fmaf(-qx[k], X.w, fmaf( qy[k], X.x, fmaf( qz[k], X.y, T.y))));
            vz[k] = fmaf(qw[k], X.w, fmaf( qx[k], X.z, fmaf(-qy[k], X.y, fmaf( qz[k], X.x, T.z))));
        }

        // ---- dynamic routing, 3 iterations ----
        float bb[8];
#pragma unroll
        for (int k = 0; k < 8; k++) bb[k] = 0.0f;

        float s0, s1, s2, s3, v0, v1, v2, v3, n2 = 0.0f;

#pragma unroll
        for (int iter = 0; iter < 3; iter++) {
            if (iter == 0) {
                // b == 0 -> uniform coupling c = 1/16
                s0 = vw[0]; s1 = vx[0]; s2 = vy[0]; s3 = vz[0];
#pragma unroll
                for (int k = 1; k < 8; k++) {
                    s0 += vw[k]; s1 += vx[k]; s2 += vy[k]; s3 += vz[k];
                }
                s0 *= 0.0625f; s1 *= 0.0625f; s2 *= 0.0625f; s3 *= 0.0625f;
            } else {
                // softmax over o, no max-subtraction (|b| bounded; f32-safe)
                float e[8], den[8];
#pragma unroll
                for (int k = 0; k < 8; k++) { e[k] = __expf(bb[k]); den[k] = e[k]; }
#pragma unroll
                for (int msk = 2; msk <= 16; msk <<= 1) {
#pragma unroll
                    for (int k = 0; k < 8; k++)
                        den[k] += __shfl_xor_sync(0xffffffffu, den[k], msk);
                }
                float c[8];
#pragma unroll
                for (int k = 0; k < 8; k++) c[k] = __fdividef(e[k], den[k]);

                s0 = s1 = s2 = s3 = 0.0f;
#pragma unroll
                for (int k = 0; k < 8; k++) {
                    s0 = fmaf(c[k], vw[k], s0);
                    s1 = fmaf(c[k], vx[k], s1);
                    s2 = fmaf(c[k], vy[k], s2);
                    s3 = fmaf(c[k], vz[k], s3);
                }
            }
            // fold the two i-halves
            s0 += __shfl_xor_sync(0xffffffffu, s0, 1);
            s1 += __shfl_xor_sync(0xffffffffu, s1, 1);
            s2 += __shfl_xor_sync(0xffffffffu, s2, 1);
            s3 += __shfl_xor_sync(0xffffffffu, s3, 1);

            // squash
            n2 = fmaf(s0, s0, fmaf(s1, s1, fmaf(s2, s2, s3 * s3)));
            const float fac = __fdividef(n2, 1.0f + n2) * rsqrtf(n2 + EPSF);
            v0 = s0 * fac; v1 = s1 * fac; v2 = s2 * fac; v3 = s3 * fac;

            // agreement update (dead on the last iteration)
            if (iter < 2) {
#pragma unroll
                for (int k = 0; k < 8; k++)
                    bb[k] = fmaf(v0, vw[k], fmaf(v1, vx[k], fmaf(v2, vy[k], fmaf(v3, vz[k], bb[k]))));
            }
        }

        // ---- activation + store (even lanes: one coalesced float4 per (n,o)) ----
        const float norm_s = sqrtf(n2 + EPSF);
        const float z = fmaf(bet, norm_s, ab);
        const float a = __fdividef(1.0f, 1.0f + __expf(-z));

        if (h == 0) {
            out4[n * 16 + o] = make_float4(v0 * a, v1 * a, v2 * a, v3 * a);
        }
    }
}

extern "C" void kernel_launch(void* const* d_in, const int* in_sizes, int n_in,
                              void* d_out, int out_size)
{
    const float* x     = (const float*)d_in[0];
    const float* quats = (const float*)d_in[1];
    const float* scale = (const float*)d_in[2];
    const float* trans = (const float*)d_in[3];
    const float* bias  = (const float*)d_in[4];
    const float* beta  = (const float*)d_in[5];
    const float* alpha = (const float*)d_in[6];

    caps_quat_kernel<<<NBLOCKS, BLOCK_THREADS>>>(x, quats, scale, trans, bias, beta, alpha,
                                                 (float*)d_out);
}

// round 6
// speedup vs baseline: 1.6513x; 1.6513x over previous
#include <cuda_runtime.h>

#define NSAMP 65536
#define EPSF 1e-8f
#define TOTAL_WARPS 4096
#define BLOCK_THREADS 128
#define NBLOCKS (TOTAL_WARPS / (BLOCK_THREADS / 32))

// Warp-per-sample, register-resident persistent kernel (R3 base).
// Lane l -> (o = l>>1, i-half h = l&1); lane owns pairs (o, i = h*8+k), k=0..7.
// Softmax denominator: reduce-scatter over o-lanes + single rcp + all-gather
// (15 shfl + 1 MUFU per iter vs 32 shfl + 8 MUFU for the naive butterfly).

__device__ __forceinline__ float fastrcp(float d) {
    float r;
    asm("rcp.approx.f32 %0, %1;" : "=f"(r) : "f"(d));
    return r;
}

__global__ void __launch_bounds__(BLOCK_THREADS)
caps_quat_kernel(const float* __restrict__ x,
                 const float* __restrict__ quats,
                 const float* __restrict__ scale,
                 const float* __restrict__ trans,
                 const float* __restrict__ bias,
                 const float* __restrict__ beta,
                 const float* __restrict__ alpha,
                 float* __restrict__ out)
{
    const int lane = threadIdx.x & 31;
    const int warp = blockIdx.x * (BLOCK_THREADS / 32) + (threadIdx.x >> 5);
    const int h    = lane & 1;       // i-half
    const int o    = lane >> 1;      // output capsule

    // ---- one-time prologue: scaled quaternion + trans for this lane's 8 pairs ----
    float qw[8], qx[8], qy[8], qz[8], t1[8], t2[8], t3[8];
    const float4* __restrict__ q4 = (const float4*)quats;
#pragma unroll
    for (int k = 0; k < 8; k++) {
        const int pi = o * 16 + h * 8 + k;
        const float4 q = __ldg(&q4[pi]);
        const float f = rsqrtf(fmaf(q.x, q.x, fmaf(q.y, q.y, fmaf(q.z, q.z, q.w * q.w))) + EPSF)
                        * __ldg(&scale[pi]);
        qw[k] = q.x * f; qx[k] = q.y * f; qy[k] = q.z * f; qz[k] = q.w * f;
        t1[k] = __ldg(&trans[pi * 3 + 0]);
        t2[k] = __ldg(&trans[pi * 3 + 1]);
        t3[k] = __ldg(&trans[pi * 3 + 2]);
    }
    const float bet = __ldg(&beta[o]);
    const float ab  = __ldg(&alpha[o]) + __ldg(&bias[o]);

    const float4* __restrict__ x4   = (const float4*)x;
    float4* __restrict__       out4 = (float4*)out;

    const bool b4  = (lane & 4)  != 0;
    const bool b8  = (lane & 8)  != 0;
    const bool b16 = (lane & 16) != 0;

#pragma unroll 1
    for (int n = warp; n < NSAMP; n += TOTAL_WARPS) {
        // ---- votes: Hamilton product from quaternion registers ----
        float vw[8], vx[8], vy[8], vz[8];
#pragma unroll
        for (int k = 0; k < 8; k++) {
            const float4 X = __ldg(&x4[n * 16 + h * 8 + k]);
            vw[k] = fmaf(qw[k], X.x, fmaf(-qx[k], X.y, fmaf(-qy[k], X.z, -qz[k] * X.w)));
            vx[k] = fmaf(qw[k], X.y, fmaf( qx[k], X.x, fmaf( qy[k], X.w, fmaf(-qz[k], X.z, t1[k]))));
            vy[k] = fmaf(qw[k], X.z, fmaf(-qx[k], X.w, fmaf( qy[k], X.x, fmaf( qz[k], X.y, t2[k]))));
            vz[k] = fmaf(qw[k], X.w, fmaf( qx[k], X.z, fmaf(-qy[k], X.y, fmaf( qz[k], X.x, t3[k]))));
        }

        // ---- dynamic routing, 3 iterations ----
        float bb[8];
#pragma unroll
        for (int k = 0; k < 8; k++) bb[k] = 0.0f;

        float s0, s1, s2, s3, v0, v1, v2, v3, n2 = 0.0f;

#pragma unroll
        for (int iter = 0; iter < 3; iter++) {
            if (iter == 0) {
                // b == 0 -> uniform coupling c = 1/16
                s0 = vw[0]; s1 = vx[0]; s2 = vy[0]; s3 = vz[0];
#pragma unroll
                for (int k = 1; k < 8; k++) {
                    s0 += vw[k]; s1 += vx[k]; s2 += vy[k]; s3 += vz[k];
                }
                s0 *= 0.0625f; s1 *= 0.0625f; s2 *= 0.0625f; s3 *= 0.0625f;
            } else {
                // softmax over o (no max-shift; |b| bounded, f32-safe).
                float e[8], r[8];
#pragma unroll
                for (int k = 0; k < 8; k++) { e[k] = __expf(bb[k]); r[k] = e[k]; }

                // --- reduce-scatter of den over o-lanes (masks 16,8,4,2) ---
                // stage msk16: 8 -> 4 values (kept k-range: b16 ? {4..7} : {0..3})
#pragma unroll
                for (int j = 0; j < 4; j++) {
                    const float snd = b16 ? r[j] : r[j + 4];        // half we don't keep
                    const float rcv = __shfl_xor_sync(0xffffffffu, snd, 16);
                    r[j] = (b16 ? r[j + 4] : r[j]) + rcv;
                }
                // stage msk8: 4 -> 2
#pragma unroll
                for (int j = 0; j < 2; j++) {
                    const float snd = b8 ? r[j] : r[j + 2];
                    const float rcv = __shfl_xor_sync(0xffffffffu, snd, 8);
                    r[j] = (b8 ? r[j + 2] : r[j]) + rcv;
                }
                // stage msk4: 2 -> 1
                {
                    const float snd = b4 ? r[0] : r[1];
                    const float rcv = __shfl_xor_sync(0xffffffffu, snd, 4);
                    r[0] = (b4 ? r[1] : r[0]) + rcv;
                }
                // stage msk2: plain butterfly (1 value)
                r[0] += __shfl_xor_sync(0xffffffffu, r[0], 2);

                // one reciprocal per lane (den for k* = 4*b16 + 2*b8 + b4)
                const float rd = fastrcp(r[0]);

                // --- all-gather of reciprocal dens (masks 4,8,16) ---
                float g0, g1, g2, g3, rden[8];
                {
                    const float p = __shfl_xor_sync(0xffffffffu, rd, 4);
                    g0 = b4 ? p : rd;          // idx bit0 = 0
                    g1 = b4 ? rd : p;          // idx bit0 = 1
                }
                {
                    const float p0 = __shfl_xor_sync(0xffffffffu, g0, 8);
                    const float p1 = __shfl_xor_sync(0xffffffffu, g1, 8);
                    g2 = b8 ? g0 : p0;  g3 = b8 ? g1 : p1;   // idx bit1 = 1
                    g0 = b8 ? p0 : g0;  g1 = b8 ? p1 : g1;   // idx bit1 = 0
                }
                {
                    const float p0 = __shfl_xor_sync(0xffffffffu, g0, 16);
                    const float p1 = __shfl_xor_sync(0xffffffffu, g1, 16);
                    const float p2 = __shfl_xor_sync(0xffffffffu, g2, 16);
                    const float p3 = __shfl_xor_sync(0xffffffffu, g3, 16);
                    rden[0] = b16 ? p0 : g0;  rden[1] = b16 ? p1 : g1;
                    rden[2] = b16 ? p2 : g2;  rden[3] = b16 ? p3 : g3;
                    rden[4] = b16 ? g0 : p0;  rden[5] = b16 ? g1 : p1;
                    rden[6] = b16 ? g2 : p2;  rden[7] = b16 ? g3 : p3;
                }

                s0 = s1 = s2 = s3 = 0.0f;
#pragma unroll
                for (int k = 0; k < 8; k++) {
                    const float c = e[k] * rden[k];
                    s0 = fmaf(c, vw[k], s0);
                    s1 = fmaf(c, vx[k], s1);
                    s2 = fmaf(c, vy[k], s2);
                    s3 = fmaf(c, vz[k], s3);
                }
            }
            // fold the two i-halves
            s0 += __shfl_xor_sync(0xffffffffu, s0, 1);
            s1 += __shfl_xor_sync(0xffffffffu, s1, 1);
            s2 += __shfl_xor_sync(0xffffffffu, s2, 1);
            s3 += __shfl_xor_sync(0xffffffffu, s3, 1);

            // squash
            n2 = fmaf(s0, s0, fmaf(s1, s1, fmaf(s2, s2, s3 * s3)));
            const float fac = n2 * fastrcp(1.0f + n2) * rsqrtf(n2 + EPSF);
            v0 = s0 * fac; v1 = s1 * fac; v2 = s2 * fac; v3 = s3 * fac;

            // agreement update (dead on the last iteration)
            if (iter < 2) {
#pragma unroll
                for (int k = 0; k < 8; k++)
                    bb[k] = fmaf(v0, vw[k], fmaf(v1, vx[k], fmaf(v2, vy[k], fmaf(v3, vz[k], bb[k]))));
            }
        }

        // ---- activation + store (even lanes: one coalesced float4 per (n,o)) ----
        const float norm_s = sqrtf(n2 + EPSF);
        const float z = fmaf(bet, norm_s, ab);
        const float a = fastrcp(1.0f + __expf(-z));

        if (h == 0) {
            out4[n * 16 + o] = make_float4(v0 * a, v1 * a, v2 * a, v3 * a);
        }
    }
}

extern "C" void kernel_launch(void* const* d_in, const int* in_sizes, int n_in,
                              void* d_out, int out_size)
{
    const float* x     = (const float*)d_in[0];
    const float* quats = (const float*)d_in[1];
    const float* scale = (const float*)d_in[2];
    const float* trans = (const float*)d_in[3];
    const float* bias  = (const float*)d_in[4];
    const float* beta  = (const float*)d_in[5];
    const float* alpha = (const float*)d_in[6];

    caps_quat_kernel<<<NBLOCKS, BLOCK_THREADS>>>(x, quats, scale, trans, bias, beta, alpha,
                                                 (float*)d_out);
}